// round 11
// baseline (speedup 1.0000x reference)
#include <cuda_runtime.h>
#include <cuda_bf16.h>
#include <cstdint>

#define B_  32
#define NN  512
#define TT  24
#define FF  64
#define FA  74
#define TF  1536      // TT*FF
#define OUTROW 1776   // TT*FA

#define BM 128
#define BN 128
#define BK 32
#define NKS (NN / BK)  // 16
#define STAGES 4

#define AROWB 80        // A row bytes in smem (64 data + 16 pad)
#define BROWB 272       // B row bytes in smem (256 data + 16 pad)
#define ASTGB (BM * AROWB)            // 10240
#define BSTGB (BK * BROWB)            // 8704
#define GEMM_SMEM (STAGES * (ASTGB + BSTGB))   // 75776

// pre_kernel block ranges
#define XBLKS ((B_ * NN * TF / 8) / 256)   // 12288
#define ADJBLKS ((NN * NN / 8) / 256)      // 128

// combine
#define CBLKS 1024
#define CITERS 4       // groups per block; CBLKS*CITERS*4 rows = 16384

__device__ float g_RW[FA];
__device__ float g_W2[TT * TT];
__device__ __nv_bfloat16 g_y[(size_t)B_ * NN * TF];
__device__ __nv_bfloat16 g_xb[(size_t)B_ * NN * TF];
__device__ __nv_bfloat16 g_adjb[(size_t)NN * NN];

// ---------------------------------------------------------------------------
__device__ __forceinline__ uint32_t smem_u32(const void* p) {
    uint32_t a;
    asm("{ .reg .u64 t; cvta.to.shared.u64 t, %1; cvt.u32.u64 %0, t; }" : "=r"(a) : "l"(p));
    return a;
}
__device__ __forceinline__ void ldsm4(uint32_t* r, uint32_t addr) {
    asm volatile("ldmatrix.sync.aligned.m8n8.x4.shared.b16 {%0,%1,%2,%3}, [%4];"
                 : "=r"(r[0]), "=r"(r[1]), "=r"(r[2]), "=r"(r[3]) : "r"(addr));
}
__device__ __forceinline__ void ldsm4t(uint32_t* r, uint32_t addr) {
    asm volatile("ldmatrix.sync.aligned.m8n8.x4.trans.shared.b16 {%0,%1,%2,%3}, [%4];"
                 : "=r"(r[0]), "=r"(r[1]), "=r"(r[2]), "=r"(r[3]) : "r"(addr));
}
__device__ __forceinline__ void mma16816(float* c, const uint32_t* a, const uint32_t* b) {
    asm volatile(
        "mma.sync.aligned.m16n8k16.row.col.f32.bf16.bf16.f32 "
        "{%0,%1,%2,%3}, {%4,%5,%6,%7}, {%8,%9}, {%0,%1,%2,%3};"
        : "+f"(c[0]), "+f"(c[1]), "+f"(c[2]), "+f"(c[3])
        : "r"(a[0]), "r"(a[1]), "r"(a[2]), "r"(a[3]), "r"(b[0]), "r"(b[1]));
}
#define CP16(dst, src) \
    asm volatile("cp.async.cg.shared.global [%0], [%1], 16;" :: "r"(dst), "l"(src) : "memory")
#define CP_COMMIT() asm volatile("cp.async.commit_group;" ::: "memory")
#define CP_WAIT2()  asm volatile("cp.async.wait_group 2;" ::: "memory")
#define CP_WAIT1()  asm volatile("cp.async.wait_group 1;" ::: "memory")

// ---------------------------------------------------------------------------
// pre_kernel: fused independent pre-work, branch on blockIdx.x.
// ---------------------------------------------------------------------------
__global__ __launch_bounds__(256)
void pre_kernel(const float* __restrict__ x, const float* __restrict__ adj,
                const float* __restrict__ alpha,
                const float* __restrict__ w, const float* __restrict__ d,
                const float* __restrict__ w2, const float* __restrict__ d2) {
    int bid = blockIdx.x;
    int tid = threadIdx.x;

    if (bid < XBLKS) {
        size_t i = (size_t)bid * 256 + tid;   // one per 8 floats
        const float4* src = (const float4*)x + i * 2;
        float4 a = src[0], b = src[1];
        __nv_bfloat162 h0 = __float22bfloat162_rn(make_float2(a.x, a.y));
        __nv_bfloat162 h1 = __float22bfloat162_rn(make_float2(a.z, a.w));
        __nv_bfloat162 h2 = __float22bfloat162_rn(make_float2(b.x, b.y));
        __nv_bfloat162 h3 = __float22bfloat162_rn(make_float2(b.z, b.w));
        ((uint4*)g_xb)[i] = make_uint4(*(uint32_t*)&h0, *(uint32_t*)&h1,
                                       *(uint32_t*)&h2, *(uint32_t*)&h3);
        return;
    }
    if (bid < XBLKS + ADJBLKS) {
        size_t i = (size_t)(bid - XBLKS) * 256 + tid;  // one per 8 floats
        int row = (int)((i * 8) / NN);
        float sc = 0.125f / (1.0f + expf(-alpha[row]));
        const float4* src = (const float4*)adj + i * 2;
        float4 a = src[0], b = src[1];
        __nv_bfloat162 h0 = __float22bfloat162_rn(make_float2(a.x * sc, a.y * sc));
        __nv_bfloat162 h1 = __float22bfloat162_rn(make_float2(a.z * sc, a.w * sc));
        __nv_bfloat162 h2 = __float22bfloat162_rn(make_float2(b.x * sc, b.y * sc));
        __nv_bfloat162 h3 = __float22bfloat162_rn(make_float2(b.z * sc, b.w * sc));
        ((uint4*)g_adjb)[i] = make_uint4(*(uint32_t*)&h0, *(uint32_t*)&h1,
                                         *(uint32_t*)&h2, *(uint32_t*)&h3);
        return;
    }
    // prep block
    __shared__ float colsum[FA];
    __shared__ float dc[FA];
    if (tid < FA) {
        float s = 0.f;
        for (int n = 0; n < FA; n++) s += w[n * FA + tid];
        colsum[tid] = s;
        dc[tid] = fminf(fmaxf(d[tid], 0.f), 1.f);
    }
    __syncthreads();
    if (tid < FA) {
        float s = 0.f;
        for (int k = 0; k < FA; k++) s += w[tid * FA + k] * dc[k] * colsum[k];
        g_RW[tid] = s;
    }
    for (int idx = tid; idx < TT * TT; idx += 256) {
        int t = idx / TT, tp = idx % TT;
        float s = 0.f;
        for (int k = 0; k < TT; k++) {
            float dk = fminf(fmaxf(d2[k], 0.f), 1.f);
            s += w2[t * TT + k] * dk * w2[tp * TT + k];
        }
        g_W2[idx] = s;
    }
}

// ---------------------------------------------------------------------------
// GEMM (unchanged from R10): y = adj_scaled @ x  (bf16 in, fp32 acc, bf16 y)
// ---------------------------------------------------------------------------
__global__ __launch_bounds__(128, 2)
void gemm_kernel() {
    extern __shared__ char smem[];
    uint32_t sb = smem_u32(smem);

    int tid = threadIdx.x, l = tid & 31, wid = tid >> 5;
    int wm = wid & 1, wn = wid >> 1;
    int b = blockIdx.z, i0 = blockIdx.y * BM, c0 = blockIdx.x * BN;
    const __nv_bfloat16* Xb = g_xb + (size_t)b * NN * TF;

#define ISSUE_STAGE(s)                                                          \
    {                                                                           \
        int buf_ = (s) & (STAGES - 1);                                          \
        int k0_ = (s) * BK;                                                     \
        uint32_t ab_ = sb + buf_ * ASTGB;                                       \
        uint32_t bb_ = sb + STAGES * ASTGB + buf_ * BSTGB;                      \
        _Pragma("unroll")                                                       \
        for (int u = 0; u < 4; u++) {                                           \
            int id = u * 128 + tid;                                             \
            int ar = id >> 2, ac = id & 3;                                      \
            CP16(ab_ + ar * AROWB + ac * 16,                                    \
                 (const char*)(g_adjb + (size_t)(i0 + ar) * NN + k0_) + ac * 16); \
            int br = id >> 4, bc = id & 15;                                     \
            CP16(bb_ + br * BROWB + bc * 16,                                    \
                 (const char*)(Xb + (size_t)(k0_ + br) * TF + c0) + bc * 16);   \
        }                                                                       \
    }

    float acc[4][8][4];
    #pragma unroll
    for (int mt = 0; mt < 4; mt++)
        #pragma unroll
        for (int nt = 0; nt < 8; nt++)
            #pragma unroll
            for (int q = 0; q < 4; q++) acc[mt][nt][q] = 0.f;

    uint32_t a_off = (uint32_t)(wm * 64 + (l & 15)) * AROWB + ((l >> 4) * 8) * 2;
    uint32_t b_off = (uint32_t)(l & 15) * BROWB + (wn * 64 + ((l >> 4) << 3)) * 2;

    ISSUE_STAGE(0); CP_COMMIT();
    ISSUE_STAGE(1); CP_COMMIT();
    ISSUE_STAGE(2); CP_COMMIT();

    for (int s = 0; s < NKS; s++) {
        int buf = s & (STAGES - 1);
        CP_WAIT2();
        __syncthreads();

        if (s + 3 < NKS) ISSUE_STAGE(s + 3);
        CP_COMMIT();

        uint32_t ab = sb + buf * ASTGB + a_off;
        uint32_t bb = sb + STAGES * ASTGB + buf * BSTGB + b_off;
        #pragma unroll
        for (int ks = 0; ks < 2; ks++) {
            uint32_t af[4][4], bf[4][4];
            #pragma unroll
            for (int mt = 0; mt < 4; mt++)
                ldsm4(af[mt], ab + mt * 16 * AROWB + ks * 32);
            #pragma unroll
            for (int n2 = 0; n2 < 4; n2++)
                ldsm4t(bf[n2], bb + ks * 16 * BROWB + n2 * 32);
            #pragma unroll
            for (int mt = 0; mt < 4; mt++)
                #pragma unroll
                for (int nt = 0; nt < 8; nt++)
                    mma16816(acc[mt][nt], af[mt], &bf[nt >> 1][(nt & 1) * 2]);
        }
    }

    int rbase = i0 + wm * 64 + (l >> 2);
    int cbase = c0 + wn * 64 + (l & 3) * 2;
    #pragma unroll
    for (int mt = 0; mt < 4; mt++) {
        #pragma unroll
        for (int nt = 0; nt < 8; nt++) {
            int i = rbase + mt * 16;
            int c = cbase + nt * 8;
            __nv_bfloat162 h0 = __float22bfloat162_rn(make_float2(acc[mt][nt][0], acc[mt][nt][1]));
            __nv_bfloat162 h1 = __float22bfloat162_rn(make_float2(acc[mt][nt][2], acc[mt][nt][3]));
            *(__nv_bfloat162*)&g_y[((size_t)b * NN + i) * TF + c] = h0;
            *(__nv_bfloat162*)&g_y[((size_t)b * NN + i + 8) * TF + c] = h1;
        }
    }
}

// ---------------------------------------------------------------------------
// Combine: persistent over 4 groups of 4 rows, double-buffered cp.async x stage.
//   out = relu(0.5*x + 0.25*xw2 + 0.25*S*RW + y), plus f>=64 strip.
// ---------------------------------------------------------------------------
__global__ __launch_bounds__(512)
void combine_kernel(const float* __restrict__ x, float* __restrict__ out) {
    __shared__ float xs[2][4][TF];      // 49152 B
    __shared__ float W2s[TT * TT];
    __shared__ float S[4][TT];
    __shared__ float RWs[FA];

    int tid = threadIdx.x;
    int ri = tid >> 7, sub = tid & 127;
    uint32_t xs_addr = smem_u32(xs);

    for (int j = tid; j < TT * TT; j += 512) W2s[j] = g_W2[j];
    if (tid < FA) RWs[tid] = g_RW[tid];

    // issue group(it) into buffer buf: 4 rows x 1536 floats, 3x16B per thread
#define CISSUE(it, buf)                                                        \
    {                                                                          \
        int row_ = (blockIdx.x + (it) * CBLKS) * 4 + ri;                       \
        const char* src_ = (const char*)(x + (size_t)row_ * TF);               \
        uint32_t dst_ = xs_addr + (uint32_t)(buf) * (4 * TF * 4)               \
                        + (uint32_t)ri * (TF * 4);                             \
        _Pragma("unroll")                                                      \
        for (int j = 0; j < 3; j++)                                            \
            CP16(dst_ + (j * 128 + sub) * 16, src_ + (j * 128 + sub) * 16);    \
    }

    CISSUE(0, 0); CP_COMMIT();

    int buf = 0;
    for (int it = 0; it < CITERS; it++) {
        if (it + 1 < CITERS) CISSUE(it + 1, buf ^ 1);
        CP_COMMIT();                 // always commit so wait_group 1 frees group it
        CP_WAIT1();
        __syncthreads();             // bar1: x(it) visible; prev compute done

        if (tid < 96) {
            int r = tid / 24;
            int t = tid - r * 24;
            float s = 0.f;
            #pragma unroll
            for (int f = 0; f < FF; f++) s += xs[buf][r][t * FF + f];
            S[r][t] = s;
        }
        __syncthreads();             // bar2: S ready

        int row0 = (blockIdx.x + it * CBLKS) * 4;
        int row = row0 + ri;
        const float* xrow = xs[buf][ri];
        const __nv_bfloat16* yr = g_y + (size_t)row * TF;
        float* outr = out + (size_t)row * OUTROW;

        int ty = sub >> 4, tx = sub & 15;
        float acc[3][4];
        #pragma unroll
        for (int r3 = 0; r3 < 3; r3++)
            #pragma unroll
            for (int q = 0; q < 4; q++) acc[r3][q] = 0.f;

        #pragma unroll
        for (int t = 0; t < TT; t++) {
            float4 xv = *(const float4*)&xrow[t * FF + tx * 4];
            float w0 = W2s[t * TT + ty];
            float w1 = W2s[t * TT + ty + 8];
            float w2v = W2s[t * TT + ty + 16];
            acc[0][0] = fmaf(w0, xv.x, acc[0][0]); acc[0][1] = fmaf(w0, xv.y, acc[0][1]);
            acc[0][2] = fmaf(w0, xv.z, acc[0][2]); acc[0][3] = fmaf(w0, xv.w, acc[0][3]);
            acc[1][0] = fmaf(w1, xv.x, acc[1][0]); acc[1][1] = fmaf(w1, xv.y, acc[1][1]);
            acc[1][2] = fmaf(w1, xv.z, acc[1][2]); acc[1][3] = fmaf(w1, xv.w, acc[1][3]);
            acc[2][0] = fmaf(w2v, xv.x, acc[2][0]); acc[2][1] = fmaf(w2v, xv.y, acc[2][1]);
            acc[2][2] = fmaf(w2v, xv.z, acc[2][2]); acc[2][3] = fmaf(w2v, xv.w, acc[2][3]);
        }

        #pragma unroll
        for (int r3 = 0; r3 < 3; r3++) {
            int tp = ty + r3 * 8;
            float sr = 0.25f * S[ri][tp];
            int f = tx * 4;
            uint2 ypk = *(const uint2*)&yr[tp * FF + f];
            __nv_bfloat162 yl = *(__nv_bfloat162*)&ypk.x;
            __nv_bfloat162 yh = *(__nv_bfloat162*)&ypk.y;
            float o0 = 0.5f * xrow[tp * FF + f]     + 0.25f * acc[r3][0] + sr * RWs[f]
                     + __bfloat162float(yl.x);
            float o1 = 0.5f * xrow[tp * FF + f + 1] + 0.25f * acc[r3][1] + sr * RWs[f + 1]
                     + __bfloat162float(yl.y);
            float o2 = 0.5f * xrow[tp * FF + f + 2] + 0.25f * acc[r3][2] + sr * RWs[f + 2]
                     + __bfloat162float(yh.x);
            float o3 = 0.5f * xrow[tp * FF + f + 3] + 0.25f * acc[r3][3] + sr * RWs[f + 3]
                     + __bfloat162float(yh.y);
            *(float2*)&outr[tp * FA + f]     = make_float2(fmaxf(o0, 0.f), fmaxf(o1, 0.f));
            *(float2*)&outr[tp * FA + f + 2] = make_float2(fmaxf(o2, 0.f), fmaxf(o3, 0.f));
        }
        // f >= 64 strip
        for (int idx = tid; idx < 4 * TT * (FA - FF); idx += 512) {
            int r = idx / (TT * (FA - FF));
            int e = idx - r * (TT * (FA - FF));
            int tp = e / (FA - FF);
            int f  = FF + e % (FA - FF);
            out[((size_t)(row0 + r)) * OUTROW + tp * FA + f] =
                fmaxf(0.25f * S[r][tp] * RWs[f], 0.f);
        }
        buf ^= 1;
    }
}

extern "C" void kernel_launch(void* const* d_in, const int* in_sizes, int n_in,
                              void* d_out, int out_size) {
    const float* x     = (const float*)d_in[0];
    const float* adj   = (const float*)d_in[1];
    const float* alpha = (const float*)d_in[2];
    const float* w     = (const float*)d_in[3];
    const float* d     = (const float*)d_in[4];
    const float* w2    = (const float*)d_in[5];
    const float* d2    = (const float*)d_in[6];
    float* out = (float*)d_out;

    cudaFuncSetAttribute(gemm_kernel, cudaFuncAttributeMaxDynamicSharedMemorySize, GEMM_SMEM);

    pre_kernel<<<XBLKS + ADJBLKS + 1, 256>>>(x, adj, alpha, w, d, w2, d2);
    dim3 grid(TF / BN, NN / BM, B_);
    gemm_kernel<<<grid, 128, GEMM_SMEM>>>();
    combine_kernel<<<CBLKS, 512>>>(x, out);
}

// round 12
// speedup vs baseline: 1.0117x; 1.0117x over previous
#include <cuda_runtime.h>
#include <cuda_bf16.h>
#include <cstdint>

#define B_  32
#define NN  512
#define TT  24
#define FF  64
#define FA  74
#define TF  1536      // TT*FF
#define OUTROW 1776   // TT*FA

#define BM 128
#define BN 128
#define BK 32
#define NKS (NN / BK)  // 16
#define STAGES 4

#define AROWB 80        // A row bytes in smem (64 data + 16 pad)
#define BROWB 272       // B row bytes in smem (256 data + 16 pad)
#define ASTGB (BM * AROWB)            // 10240
#define BSTGB (BK * BROWB)            // 8704
#define GEMM_SMEM (STAGES * (ASTGB + BSTGB))   // 75776

// pre_kernel block ranges
#define XBLKS ((B_ * NN * TF / 8) / 256)   // 12288
#define ADJBLKS ((NN * NN / 8) / 256)      // 128

// combine: 2048 blocks x 4 groups x 2 rows = 16384 rows
#define CBLKS 2048
#define CITERS 4

__device__ float g_RW[FA];
__device__ float g_W2[TT * TT];
__device__ __nv_bfloat16 g_y[(size_t)B_ * NN * TF];
__device__ __nv_bfloat16 g_xb[(size_t)B_ * NN * TF];
__device__ __nv_bfloat16 g_adjb[(size_t)NN * NN];

// ---------------------------------------------------------------------------
__device__ __forceinline__ uint32_t smem_u32(const void* p) {
    uint32_t a;
    asm("{ .reg .u64 t; cvta.to.shared.u64 t, %1; cvt.u32.u64 %0, t; }" : "=r"(a) : "l"(p));
    return a;
}
__device__ __forceinline__ void ldsm4(uint32_t* r, uint32_t addr) {
    asm volatile("ldmatrix.sync.aligned.m8n8.x4.shared.b16 {%0,%1,%2,%3}, [%4];"
                 : "=r"(r[0]), "=r"(r[1]), "=r"(r[2]), "=r"(r[3]) : "r"(addr));
}
__device__ __forceinline__ void ldsm4t(uint32_t* r, uint32_t addr) {
    asm volatile("ldmatrix.sync.aligned.m8n8.x4.trans.shared.b16 {%0,%1,%2,%3}, [%4];"
                 : "=r"(r[0]), "=r"(r[1]), "=r"(r[2]), "=r"(r[3]) : "r"(addr));
}
__device__ __forceinline__ void mma16816(float* c, const uint32_t* a, const uint32_t* b) {
    asm volatile(
        "mma.sync.aligned.m16n8k16.row.col.f32.bf16.bf16.f32 "
        "{%0,%1,%2,%3}, {%4,%5,%6,%7}, {%8,%9}, {%0,%1,%2,%3};"
        : "+f"(c[0]), "+f"(c[1]), "+f"(c[2]), "+f"(c[3])
        : "r"(a[0]), "r"(a[1]), "r"(a[2]), "r"(a[3]), "r"(b[0]), "r"(b[1]));
}
#define CP16(dst, src) \
    asm volatile("cp.async.cg.shared.global [%0], [%1], 16;" :: "r"(dst), "l"(src) : "memory")
#define CP_COMMIT() asm volatile("cp.async.commit_group;" ::: "memory")
#define CP_WAIT2()  asm volatile("cp.async.wait_group 2;" ::: "memory")
#define CP_WAIT1()  asm volatile("cp.async.wait_group 1;" ::: "memory")

// ---------------------------------------------------------------------------
// pre_kernel: fused independent pre-work, branch on blockIdx.x.
// ---------------------------------------------------------------------------
__global__ __launch_bounds__(256)
void pre_kernel(const float* __restrict__ x, const float* __restrict__ adj,
                const float* __restrict__ alpha,
                const float* __restrict__ w, const float* __restrict__ d,
                const float* __restrict__ w2, const float* __restrict__ d2) {
    int bid = blockIdx.x;
    int tid = threadIdx.x;

    if (bid < XBLKS) {
        size_t i = (size_t)bid * 256 + tid;   // one per 8 floats
        const float4* src = (const float4*)x + i * 2;
        float4 a = src[0], b = src[1];
        __nv_bfloat162 h0 = __float22bfloat162_rn(make_float2(a.x, a.y));
        __nv_bfloat162 h1 = __float22bfloat162_rn(make_float2(a.z, a.w));
        __nv_bfloat162 h2 = __float22bfloat162_rn(make_float2(b.x, b.y));
        __nv_bfloat162 h3 = __float22bfloat162_rn(make_float2(b.z, b.w));
        ((uint4*)g_xb)[i] = make_uint4(*(uint32_t*)&h0, *(uint32_t*)&h1,
                                       *(uint32_t*)&h2, *(uint32_t*)&h3);
        return;
    }
    if (bid < XBLKS + ADJBLKS) {
        size_t i = (size_t)(bid - XBLKS) * 256 + tid;  // one per 8 floats
        int row = (int)((i * 8) / NN);
        float sc = 0.125f / (1.0f + expf(-alpha[row]));
        const float4* src = (const float4*)adj + i * 2;
        float4 a = src[0], b = src[1];
        __nv_bfloat162 h0 = __float22bfloat162_rn(make_float2(a.x * sc, a.y * sc));
        __nv_bfloat162 h1 = __float22bfloat162_rn(make_float2(a.z * sc, a.w * sc));
        __nv_bfloat162 h2 = __float22bfloat162_rn(make_float2(b.x * sc, b.y * sc));
        __nv_bfloat162 h3 = __float22bfloat162_rn(make_float2(b.z * sc, b.w * sc));
        ((uint4*)g_adjb)[i] = make_uint4(*(uint32_t*)&h0, *(uint32_t*)&h1,
                                         *(uint32_t*)&h2, *(uint32_t*)&h3);
        return;
    }
    // prep block
    __shared__ float colsum[FA];
    __shared__ float dc[FA];
    if (tid < FA) {
        float s = 0.f;
        for (int n = 0; n < FA; n++) s += w[n * FA + tid];
        colsum[tid] = s;
        dc[tid] = fminf(fmaxf(d[tid], 0.f), 1.f);
    }
    __syncthreads();
    if (tid < FA) {
        float s = 0.f;
        for (int k = 0; k < FA; k++) s += w[tid * FA + k] * dc[k] * colsum[k];
        g_RW[tid] = s;
    }
    for (int idx = tid; idx < TT * TT; idx += 256) {
        int t = idx / TT, tp = idx % TT;
        float s = 0.f;
        for (int k = 0; k < TT; k++) {
            float dk = fminf(fmaxf(d2[k], 0.f), 1.f);
            s += w2[t * TT + k] * dk * w2[tp * TT + k];
        }
        g_W2[idx] = s;
    }
}

// ---------------------------------------------------------------------------
// GEMM (unchanged from R10): y = adj_scaled @ x  (bf16 in, fp32 acc, bf16 y)
// ---------------------------------------------------------------------------
__global__ __launch_bounds__(128, 2)
void gemm_kernel() {
    extern __shared__ char smem[];
    uint32_t sb = smem_u32(smem);

    int tid = threadIdx.x, l = tid & 31, wid = tid >> 5;
    int wm = wid & 1, wn = wid >> 1;
    int b = blockIdx.z, i0 = blockIdx.y * BM, c0 = blockIdx.x * BN;
    const __nv_bfloat16* Xb = g_xb + (size_t)b * NN * TF;

#define ISSUE_STAGE(s)                                                          \
    {                                                                           \
        int buf_ = (s) & (STAGES - 1);                                          \
        int k0_ = (s) * BK;                                                     \
        uint32_t ab_ = sb + buf_ * ASTGB;                                       \
        uint32_t bb_ = sb + STAGES * ASTGB + buf_ * BSTGB;                      \
        _Pragma("unroll")                                                       \
        for (int u = 0; u < 4; u++) {                                           \
            int id = u * 128 + tid;                                             \
            int ar = id >> 2, ac = id & 3;                                      \
            CP16(ab_ + ar * AROWB + ac * 16,                                    \
                 (const char*)(g_adjb + (size_t)(i0 + ar) * NN + k0_) + ac * 16); \
            int br = id >> 4, bc = id & 15;                                     \
            CP16(bb_ + br * BROWB + bc * 16,                                    \
                 (const char*)(Xb + (size_t)(k0_ + br) * TF + c0) + bc * 16);   \
        }                                                                       \
    }

    float acc[4][8][4];
    #pragma unroll
    for (int mt = 0; mt < 4; mt++)
        #pragma unroll
        for (int nt = 0; nt < 8; nt++)
            #pragma unroll
            for (int q = 0; q < 4; q++) acc[mt][nt][q] = 0.f;

    uint32_t a_off = (uint32_t)(wm * 64 + (l & 15)) * AROWB + ((l >> 4) * 8) * 2;
    uint32_t b_off = (uint32_t)(l & 15) * BROWB + (wn * 64 + ((l >> 4) << 3)) * 2;

    ISSUE_STAGE(0); CP_COMMIT();
    ISSUE_STAGE(1); CP_COMMIT();
    ISSUE_STAGE(2); CP_COMMIT();

    for (int s = 0; s < NKS; s++) {
        int buf = s & (STAGES - 1);
        CP_WAIT2();
        __syncthreads();

        if (s + 3 < NKS) ISSUE_STAGE(s + 3);
        CP_COMMIT();

        uint32_t ab = sb + buf * ASTGB + a_off;
        uint32_t bb = sb + STAGES * ASTGB + buf * BSTGB + b_off;
        #pragma unroll
        for (int ks = 0; ks < 2; ks++) {
            uint32_t af[4][4], bf[4][4];
            #pragma unroll
            for (int mt = 0; mt < 4; mt++)
                ldsm4(af[mt], ab + mt * 16 * AROWB + ks * 32);
            #pragma unroll
            for (int n2 = 0; n2 < 4; n2++)
                ldsm4t(bf[n2], bb + ks * 16 * BROWB + n2 * 32);
            #pragma unroll
            for (int mt = 0; mt < 4; mt++)
                #pragma unroll
                for (int nt = 0; nt < 8; nt++)
                    mma16816(acc[mt][nt], af[mt], &bf[nt >> 1][(nt & 1) * 2]);
        }
    }

    int rbase = i0 + wm * 64 + (l >> 2);
    int cbase = c0 + wn * 64 + (l & 3) * 2;
    #pragma unroll
    for (int mt = 0; mt < 4; mt++) {
        #pragma unroll
        for (int nt = 0; nt < 8; nt++) {
            int i = rbase + mt * 16;
            int c = cbase + nt * 8;
            __nv_bfloat162 h0 = __float22bfloat162_rn(make_float2(acc[mt][nt][0], acc[mt][nt][1]));
            __nv_bfloat162 h1 = __float22bfloat162_rn(make_float2(acc[mt][nt][2], acc[mt][nt][3]));
            *(__nv_bfloat162*)&g_y[((size_t)b * NN + i) * TF + c] = h0;
            *(__nv_bfloat162*)&g_y[((size_t)b * NN + i + 8) * TF + c] = h1;
        }
    }
}

// ---------------------------------------------------------------------------
// Combine: 256 threads, 2 rows per group, 4 groups, double-buffered cp.async.
// smem ~27KB -> 8 blocks/SM (full 2048 threads) AND cross-group overlap.
//   out = relu(0.5*x + 0.25*xw2 + 0.25*S*RW + y), plus f>=64 strip.
// ---------------------------------------------------------------------------
__global__ __launch_bounds__(256)
void combine_kernel(const float* __restrict__ x, float* __restrict__ out) {
    __shared__ float xs[2][2][TF];      // 24576 B
    __shared__ float W2s[TT * TT];
    __shared__ float S[2][TT];
    __shared__ float RWs[FA];

    int tid = threadIdx.x;
    int ri = tid >> 7, sub = tid & 127;
    uint32_t xs_addr = smem_u32(xs);

    for (int j = tid; j < TT * TT; j += 256) W2s[j] = g_W2[j];
    if (tid < FA) RWs[tid] = g_RW[tid];

    // issue group(it) into buffer buf: 2 rows x 1536 floats, 3x16B per thread
#define CISSUE(it, buf)                                                        \
    {                                                                          \
        int row_ = (blockIdx.x + (it) * CBLKS) * 2 + ri;                       \
        const char* src_ = (const char*)(x + (size_t)row_ * TF);               \
        uint32_t dst_ = xs_addr + (uint32_t)(buf) * (2 * TF * 4)               \
                        + (uint32_t)ri * (TF * 4);                             \
        _Pragma("unroll")                                                      \
        for (int j = 0; j < 3; j++)                                            \
            CP16(dst_ + (j * 128 + sub) * 16, src_ + (j * 128 + sub) * 16);    \
    }

    CISSUE(0, 0); CP_COMMIT();

    int buf = 0;
    for (int it = 0; it < CITERS; it++) {
        if (it + 1 < CITERS) CISSUE(it + 1, buf ^ 1);
        CP_COMMIT();                 // always commit so wait_group 1 frees group it
        CP_WAIT1();
        __syncthreads();             // x(it) visible; prev compute done with buf

        if (tid < 48) {
            int r = tid / 24;
            int t = tid - r * 24;
            float s = 0.f;
            #pragma unroll
            for (int f = 0; f < FF; f++) s += xs[buf][r][t * FF + f];
            S[r][t] = s;
        }
        __syncthreads();             // S ready

        int row0 = (blockIdx.x + it * CBLKS) * 2;
        int row = row0 + ri;
        const float* xrow = xs[buf][ri];
        const __nv_bfloat16* yr = g_y + (size_t)row * TF;
        float* outr = out + (size_t)row * OUTROW;

        int ty = sub >> 4, tx = sub & 15;
        float acc[3][4];
        #pragma unroll
        for (int r3 = 0; r3 < 3; r3++)
            #pragma unroll
            for (int q = 0; q < 4; q++) acc[r3][q] = 0.f;

        #pragma unroll
        for (int t = 0; t < TT; t++) {
            float4 xv = *(const float4*)&xrow[t * FF + tx * 4];
            float w0 = W2s[t * TT + ty];
            float w1 = W2s[t * TT + ty + 8];
            float w2v = W2s[t * TT + ty + 16];
            acc[0][0] = fmaf(w0, xv.x, acc[0][0]); acc[0][1] = fmaf(w0, xv.y, acc[0][1]);
            acc[0][2] = fmaf(w0, xv.z, acc[0][2]); acc[0][3] = fmaf(w0, xv.w, acc[0][3]);
            acc[1][0] = fmaf(w1, xv.x, acc[1][0]); acc[1][1] = fmaf(w1, xv.y, acc[1][1]);
            acc[1][2] = fmaf(w1, xv.z, acc[1][2]); acc[1][3] = fmaf(w1, xv.w, acc[1][3]);
            acc[2][0] = fmaf(w2v, xv.x, acc[2][0]); acc[2][1] = fmaf(w2v, xv.y, acc[2][1]);
            acc[2][2] = fmaf(w2v, xv.z, acc[2][2]); acc[2][3] = fmaf(w2v, xv.w, acc[2][3]);
        }

        #pragma unroll
        for (int r3 = 0; r3 < 3; r3++) {
            int tp = ty + r3 * 8;
            float sr = 0.25f * S[ri][tp];
            int f = tx * 4;
            uint2 ypk = *(const uint2*)&yr[tp * FF + f];
            __nv_bfloat162 yl = *(__nv_bfloat162*)&ypk.x;
            __nv_bfloat162 yh = *(__nv_bfloat162*)&ypk.y;
            float o0 = 0.5f * xrow[tp * FF + f]     + 0.25f * acc[r3][0] + sr * RWs[f]
                     + __bfloat162float(yl.x);
            float o1 = 0.5f * xrow[tp * FF + f + 1] + 0.25f * acc[r3][1] + sr * RWs[f + 1]
                     + __bfloat162float(yl.y);
            float o2 = 0.5f * xrow[tp * FF + f + 2] + 0.25f * acc[r3][2] + sr * RWs[f + 2]
                     + __bfloat162float(yh.x);
            float o3 = 0.5f * xrow[tp * FF + f + 3] + 0.25f * acc[r3][3] + sr * RWs[f + 3]
                     + __bfloat162float(yh.y);
            *(float2*)&outr[tp * FA + f]     = make_float2(fmaxf(o0, 0.f), fmaxf(o1, 0.f));
            *(float2*)&outr[tp * FA + f + 2] = make_float2(fmaxf(o2, 0.f), fmaxf(o3, 0.f));
        }
        // f >= 64 strip: 2 rows x 240 elems = 480 over 256 threads
        for (int idx = tid; idx < 2 * TT * (FA - FF); idx += 256) {
            int r = idx / (TT * (FA - FF));
            int e = idx - r * (TT * (FA - FF));
            int tp = e / (FA - FF);
            int f  = FF + e % (FA - FF);
            out[((size_t)(row0 + r)) * OUTROW + tp * FA + f] =
                fmaxf(0.25f * S[r][tp] * RWs[f], 0.f);
        }
        buf ^= 1;
    }
}

extern "C" void kernel_launch(void* const* d_in, const int* in_sizes, int n_in,
                              void* d_out, int out_size) {
    const float* x     = (const float*)d_in[0];
    const float* adj   = (const float*)d_in[1];
    const float* alpha = (const float*)d_in[2];
    const float* w     = (const float*)d_in[3];
    const float* d     = (const float*)d_in[4];
    const float* w2    = (const float*)d_in[5];
    const float* d2    = (const float*)d_in[6];
    float* out = (float*)d_out;

    cudaFuncSetAttribute(gemm_kernel, cudaFuncAttributeMaxDynamicSharedMemorySize, GEMM_SMEM);

    pre_kernel<<<XBLKS + ADJBLKS + 1, 256>>>(x, adj, alpha, w, d, w2, d2);
    dim3 grid(TF / BN, NN / BM, B_);
    gemm_kernel<<<grid, 128, GEMM_SMEM>>>();
    combine_kernel<<<CBLKS, 256>>>(x, out);
}

// round 13
// speedup vs baseline: 1.0204x; 1.0086x over previous
#include <cuda_runtime.h>
#include <cuda_bf16.h>
#include <cstdint>

#define B_  32
#define NN  512
#define TT  24
#define FF  64
#define FA  74
#define TF  1536      // TT*FF
#define OUTROW 1776   // TT*FA

#define BM 128
#define BN 128
#define BK 64
#define NKS (NN / BK)  // 8
#define STAGES 3

#define AROWB 144       // A row bytes in smem (128 data + 16 pad)
#define BROWB 272       // B row bytes in smem (256 data + 16 pad)
#define ASTGB (BM * AROWB)            // 18432
#define BSTGB (BK * BROWB)            // 17408
#define GEMM_SMEM (STAGES * (ASTGB + BSTGB))   // 107520

// pre_kernel block ranges
#define XBLKS ((B_ * NN * TF / 8) / 256)   // 12288
#define ADJBLKS ((NN * NN / 8) / 256)      // 128

__device__ float g_RW[FA];
__device__ float g_W2[TT * TT];
__device__ __nv_bfloat16 g_y[(size_t)B_ * NN * TF];
__device__ __nv_bfloat16 g_xb[(size_t)B_ * NN * TF];
__device__ __nv_bfloat16 g_adjb[(size_t)NN * NN];

// ---------------------------------------------------------------------------
__device__ __forceinline__ uint32_t smem_u32(const void* p) {
    uint32_t a;
    asm("{ .reg .u64 t; cvta.to.shared.u64 t, %1; cvt.u32.u64 %0, t; }" : "=r"(a) : "l"(p));
    return a;
}
__device__ __forceinline__ void ldsm4(uint32_t* r, uint32_t addr) {
    asm volatile("ldmatrix.sync.aligned.m8n8.x4.shared.b16 {%0,%1,%2,%3}, [%4];"
                 : "=r"(r[0]), "=r"(r[1]), "=r"(r[2]), "=r"(r[3]) : "r"(addr));
}
__device__ __forceinline__ void ldsm4t(uint32_t* r, uint32_t addr) {
    asm volatile("ldmatrix.sync.aligned.m8n8.x4.trans.shared.b16 {%0,%1,%2,%3}, [%4];"
                 : "=r"(r[0]), "=r"(r[1]), "=r"(r[2]), "=r"(r[3]) : "r"(addr));
}
__device__ __forceinline__ void mma16816(float* c, const uint32_t* a, const uint32_t* b) {
    asm volatile(
        "mma.sync.aligned.m16n8k16.row.col.f32.bf16.bf16.f32 "
        "{%0,%1,%2,%3}, {%4,%5,%6,%7}, {%8,%9}, {%0,%1,%2,%3};"
        : "+f"(c[0]), "+f"(c[1]), "+f"(c[2]), "+f"(c[3])
        : "r"(a[0]), "r"(a[1]), "r"(a[2]), "r"(a[3]), "r"(b[0]), "r"(b[1]));
}
#define CP16(dst, src) \
    asm volatile("cp.async.cg.shared.global [%0], [%1], 16;" :: "r"(dst), "l"(src) : "memory")
#define CP_COMMIT() asm volatile("cp.async.commit_group;" ::: "memory")
#define CP_WAIT1()  asm volatile("cp.async.wait_group 1;" ::: "memory")

// ---------------------------------------------------------------------------
// pre_kernel: fused independent pre-work, branch on blockIdx.x.
// ---------------------------------------------------------------------------
__global__ __launch_bounds__(256)
void pre_kernel(const float* __restrict__ x, const float* __restrict__ adj,
                const float* __restrict__ alpha,
                const float* __restrict__ w, const float* __restrict__ d,
                const float* __restrict__ w2, const float* __restrict__ d2) {
    int bid = blockIdx.x;
    int tid = threadIdx.x;

    if (bid < XBLKS) {
        size_t i = (size_t)bid * 256 + tid;   // one per 8 floats
        const float4* src = (const float4*)x + i * 2;
        float4 a = src[0], b = src[1];
        __nv_bfloat162 h0 = __float22bfloat162_rn(make_float2(a.x, a.y));
        __nv_bfloat162 h1 = __float22bfloat162_rn(make_float2(a.z, a.w));
        __nv_bfloat162 h2 = __float22bfloat162_rn(make_float2(b.x, b.y));
        __nv_bfloat162 h3 = __float22bfloat162_rn(make_float2(b.z, b.w));
        ((uint4*)g_xb)[i] = make_uint4(*(uint32_t*)&h0, *(uint32_t*)&h1,
                                       *(uint32_t*)&h2, *(uint32_t*)&h3);
        return;
    }
    if (bid < XBLKS + ADJBLKS) {
        size_t i = (size_t)(bid - XBLKS) * 256 + tid;  // one per 8 floats
        int row = (int)((i * 8) / NN);
        float sc = 0.125f / (1.0f + expf(-alpha[row]));
        const float4* src = (const float4*)adj + i * 2;
        float4 a = src[0], b = src[1];
        __nv_bfloat162 h0 = __float22bfloat162_rn(make_float2(a.x * sc, a.y * sc));
        __nv_bfloat162 h1 = __float22bfloat162_rn(make_float2(a.z * sc, a.w * sc));
        __nv_bfloat162 h2 = __float22bfloat162_rn(make_float2(b.x * sc, b.y * sc));
        __nv_bfloat162 h3 = __float22bfloat162_rn(make_float2(b.z * sc, b.w * sc));
        ((uint4*)g_adjb)[i] = make_uint4(*(uint32_t*)&h0, *(uint32_t*)&h1,
                                         *(uint32_t*)&h2, *(uint32_t*)&h3);
        return;
    }
    // prep block
    __shared__ float colsum[FA];
    __shared__ float dc[FA];
    if (tid < FA) {
        float s = 0.f;
        for (int n = 0; n < FA; n++) s += w[n * FA + tid];
        colsum[tid] = s;
        dc[tid] = fminf(fmaxf(d[tid], 0.f), 1.f);
    }
    __syncthreads();
    if (tid < FA) {
        float s = 0.f;
        for (int k = 0; k < FA; k++) s += w[tid * FA + k] * dc[k] * colsum[k];
        g_RW[tid] = s;
    }
    for (int idx = tid; idx < TT * TT; idx += 256) {
        int t = idx / TT, tp = idx % TT;
        float s = 0.f;
        for (int k = 0; k < TT; k++) {
            float dk = fminf(fmaxf(d2[k], 0.f), 1.f);
            s += w2[t * TT + k] * dk * w2[tp * TT + k];
        }
        g_W2[idx] = s;
    }
}

// ---------------------------------------------------------------------------
// GEMM: y = adj_scaled @ x  (bf16 in, fp32 acc, bf16 y)
// CTA 128x128, 4 warps, warp tile 64x64, 8 K-stages of 64, 3-stage cp.async.
// ---------------------------------------------------------------------------
__global__ __launch_bounds__(128, 2)
void gemm_kernel() {
    extern __shared__ char smem[];
    uint32_t sb = smem_u32(smem);

    int tid = threadIdx.x, l = tid & 31, wid = tid >> 5;
    int wm = wid & 1, wn = wid >> 1;
    int b = blockIdx.z, i0 = blockIdx.y * BM, c0 = blockIdx.x * BN;
    const __nv_bfloat16* Xb = g_xb + (size_t)b * NN * TF;

#define ISSUE_STAGE(s)                                                          \
    {                                                                           \
        int buf_ = (s) % STAGES;                                                \
        int k0_ = (s) * BK;                                                     \
        uint32_t ab_ = sb + buf_ * ASTGB;                                       \
        uint32_t bb_ = sb + STAGES * ASTGB + buf_ * BSTGB;                      \
        _Pragma("unroll")                                                       \
        for (int u = 0; u < 8; u++) {                                           \
            int id = u * 128 + tid;                                             \
            int ar = id >> 3, ac = id & 7;                                      \
            CP16(ab_ + ar * AROWB + ac * 16,                                    \
                 (const char*)(g_adjb + (size_t)(i0 + ar) * NN + k0_) + ac * 16); \
            int br = id >> 4, bc = id & 15;                                     \
            CP16(bb_ + br * BROWB + bc * 16,                                    \
                 (const char*)(Xb + (size_t)(k0_ + br) * TF + c0) + bc * 16);   \
        }                                                                       \
    }

    float acc[4][8][4];
    #pragma unroll
    for (int mt = 0; mt < 4; mt++)
        #pragma unroll
        for (int nt = 0; nt < 8; nt++)
            #pragma unroll
            for (int q = 0; q < 4; q++) acc[mt][nt][q] = 0.f;

    uint32_t a_off = (uint32_t)(wm * 64 + (l & 15)) * AROWB + ((l >> 4) * 8) * 2;
    uint32_t b_off = (uint32_t)(l & 15) * BROWB + (wn * 64 + ((l >> 4) << 3)) * 2;

    ISSUE_STAGE(0); CP_COMMIT();
    ISSUE_STAGE(1); CP_COMMIT();

    for (int s = 0; s < NKS; s++) {
        int buf = s % STAGES;
        CP_WAIT1();
        __syncthreads();

        if (s + 2 < NKS) ISSUE_STAGE(s + 2);
        CP_COMMIT();   // always commit so wait_group 1 tracks stage s exactly

        uint32_t ab = sb + buf * ASTGB + a_off;
        uint32_t bb = sb + STAGES * ASTGB + buf * BSTGB + b_off;
        #pragma unroll
        for (int ks = 0; ks < 4; ks++) {
            uint32_t af[4][4], bf[4][4];
            #pragma unroll
            for (int mt = 0; mt < 4; mt++)
                ldsm4(af[mt], ab + mt * 16 * AROWB + ks * 32);
            #pragma unroll
            for (int n2 = 0; n2 < 4; n2++)
                ldsm4t(bf[n2], bb + ks * 16 * BROWB + n2 * 32);
            #pragma unroll
            for (int mt = 0; mt < 4; mt++)
                #pragma unroll
                for (int nt = 0; nt < 8; nt++)
                    mma16816(acc[mt][nt], af[mt], &bf[nt >> 1][(nt & 1) * 2]);
        }
        // no trailing barrier — next iteration's top barrier protects the ring
    }

    int rbase = i0 + wm * 64 + (l >> 2);
    int cbase = c0 + wn * 64 + (l & 3) * 2;
    #pragma unroll
    for (int mt = 0; mt < 4; mt++) {
        #pragma unroll
        for (int nt = 0; nt < 8; nt++) {
            int i = rbase + mt * 16;
            int c = cbase + nt * 8;
            __nv_bfloat162 h0 = __float22bfloat162_rn(make_float2(acc[mt][nt][0], acc[mt][nt][1]));
            __nv_bfloat162 h1 = __float22bfloat162_rn(make_float2(acc[mt][nt][2], acc[mt][nt][3]));
            *(__nv_bfloat162*)&g_y[((size_t)b * NN + i) * TF + c] = h0;
            *(__nv_bfloat162*)&g_y[((size_t)b * NN + i + 8) * TF + c] = h1;
        }
    }
}

// ---------------------------------------------------------------------------
// Combine (R10 best config): 4 rows per block, 512 threads.
//   out = relu(0.5*x + 0.25*xw2 + 0.25*S*RW + y), plus f>=64 strip.
// ---------------------------------------------------------------------------
__global__ __launch_bounds__(512)
void combine_kernel(const float* __restrict__ x, float* __restrict__ out) {
    int row0 = blockIdx.x * 4;
    int tid = threadIdx.x;
    int ri = tid >> 7, sub = tid & 127;
    int row = row0 + ri;
    const float* xr = x + (size_t)row * TF;
    const __nv_bfloat16* yr = g_y + (size_t)row * TF;
    float* outr = out + (size_t)row * OUTROW;

    __shared__ float xs[4][TF];
    __shared__ float W2s[TT * TT];
    __shared__ float S[4][TT];
    __shared__ float RWs[FA];

    #pragma unroll
    for (int j = 0; j < 3; j++)
        ((float4*)xs[ri])[j * 128 + sub] = ((const float4*)xr)[j * 128 + sub];
    for (int j = tid; j < TT * TT; j += 512) W2s[j] = g_W2[j];
    if (tid < FA) RWs[tid] = g_RW[tid];
    __syncthreads();

    if (tid < 96) {
        int r = tid / 24;
        int t = tid - r * 24;
        float s = 0.f;
        #pragma unroll
        for (int f = 0; f < FF; f++) s += xs[r][t * FF + f];
        S[r][t] = s;
    }
    __syncthreads();

    int ty = sub >> 4, tx = sub & 15;
    float acc[3][4];
    #pragma unroll
    for (int r3 = 0; r3 < 3; r3++)
        #pragma unroll
        for (int q = 0; q < 4; q++) acc[r3][q] = 0.f;

    #pragma unroll
    for (int t = 0; t < TT; t++) {
        float4 xv = *(const float4*)&xs[ri][t * FF + tx * 4];
        float w0 = W2s[t * TT + ty];
        float w1 = W2s[t * TT + ty + 8];
        float w2v = W2s[t * TT + ty + 16];
        acc[0][0] = fmaf(w0, xv.x, acc[0][0]); acc[0][1] = fmaf(w0, xv.y, acc[0][1]);
        acc[0][2] = fmaf(w0, xv.z, acc[0][2]); acc[0][3] = fmaf(w0, xv.w, acc[0][3]);
        acc[1][0] = fmaf(w1, xv.x, acc[1][0]); acc[1][1] = fmaf(w1, xv.y, acc[1][1]);
        acc[1][2] = fmaf(w1, xv.z, acc[1][2]); acc[1][3] = fmaf(w1, xv.w, acc[1][3]);
        acc[2][0] = fmaf(w2v, xv.x, acc[2][0]); acc[2][1] = fmaf(w2v, xv.y, acc[2][1]);
        acc[2][2] = fmaf(w2v, xv.z, acc[2][2]); acc[2][3] = fmaf(w2v, xv.w, acc[2][3]);
    }

    #pragma unroll
    for (int r3 = 0; r3 < 3; r3++) {
        int tp = ty + r3 * 8;
        float sr = 0.25f * S[ri][tp];
        int f = tx * 4;
        uint2 ypk = *(const uint2*)&yr[tp * FF + f];
        __nv_bfloat162 yl = *(__nv_bfloat162*)&ypk.x;
        __nv_bfloat162 yh = *(__nv_bfloat162*)&ypk.y;
        float o0 = 0.5f * xs[ri][tp * FF + f]     + 0.25f * acc[r3][0] + sr * RWs[f]
                 + __bfloat162float(yl.x);
        float o1 = 0.5f * xs[ri][tp * FF + f + 1] + 0.25f * acc[r3][1] + sr * RWs[f + 1]
                 + __bfloat162float(yl.y);
        float o2 = 0.5f * xs[ri][tp * FF + f + 2] + 0.25f * acc[r3][2] + sr * RWs[f + 2]
                 + __bfloat162float(yh.x);
        float o3 = 0.5f * xs[ri][tp * FF + f + 3] + 0.25f * acc[r3][3] + sr * RWs[f + 3]
                 + __bfloat162float(yh.y);
        *(float2*)&outr[tp * FA + f]     = make_float2(fmaxf(o0, 0.f), fmaxf(o1, 0.f));
        *(float2*)&outr[tp * FA + f + 2] = make_float2(fmaxf(o2, 0.f), fmaxf(o3, 0.f));
    }
    for (int idx = tid; idx < 4 * TT * (FA - FF); idx += 512) {
        int r = idx / (TT * (FA - FF));
        int e = idx - r * (TT * (FA - FF));
        int tp = e / (FA - FF);
        int f  = FF + e % (FA - FF);
        out[((size_t)(row0 + r)) * OUTROW + tp * FA + f] =
            fmaxf(0.25f * S[r][tp] * RWs[f], 0.f);
    }
}

extern "C" void kernel_launch(void* const* d_in, const int* in_sizes, int n_in,
                              void* d_out, int out_size) {
    const float* x     = (const float*)d_in[0];
    const float* adj   = (const float*)d_in[1];
    const float* alpha = (const float*)d_in[2];
    const float* w     = (const float*)d_in[3];
    const float* d     = (const float*)d_in[4];
    const float* w2    = (const float*)d_in[5];
    const float* d2    = (const float*)d_in[6];
    float* out = (float*)d_out;

    cudaFuncSetAttribute(gemm_kernel, cudaFuncAttributeMaxDynamicSharedMemorySize, GEMM_SMEM);

    pre_kernel<<<XBLKS + ADJBLKS + 1, 256>>>(x, adj, alpha, w, d, w2, d2);
    dim3 grid(TF / BN, NN / BM, B_);
    gemm_kernel<<<grid, 128, GEMM_SMEM>>>();
    combine_kernel<<<B_ * NN / 4, 512>>>(x, out);
}